// round 3
// baseline (speedup 1.0000x reference)
#include <cuda_runtime.h>
#include <cstdint>
#include <cstddef>

#define Bc 4
#define Nc 2048
#define Ec 32768
#define Dc 128
#define Lc 3
#define NRELc 1000
#define BEc (Bc*Ec)          // 131072 edges total

// ---------------- static device scratch (no allocations allowed) ----------------
__device__ float    g_h[Bc*Nc*Dc];          // node states (4 MB)
__device__ float    g_aggr[Bc*Nc*Dc];       // per-layer aggregation (4 MB)
__device__ unsigned g_mx[Bc*Nc];            // encoded float max per target
__device__ float    g_sm[Bc*Nc];            // softmax denominator per target
__device__ float    g_raw[(size_t)BEc*Dc];  // raw messages (64 MB)
__device__ float    g_att[BEc];
__device__ float    g_gd[BEc];              // gate * den * edge_mask
__device__ float    g_attc[Lc*BEc];         // attention constant per (k, edge)
__device__ float    g_relMsg[Lc*NRELc*Dc];  // h_r@W4 + msg_b per (k, rel)
__device__ float    g_relDen[NRELc*Dc];     // h_r@den_W1[0:128] per rel
__device__ float    g_relBeta[NRELc];
__device__ float    g_relAtt[Lc*NRELc];
__device__ float    g_rqDen[Bc*Dc];         // rq@den_W1[128:256] + den_b1 per batch
__device__ float    g_rqBeta[Bc];
__device__ float    g_rqAtt[Lc*Bc];
__device__ float    g_s3[Lc*Dc];            // colsum of W3 per layer
__device__ int      g_mflag;                // 1 = masks are 1-byte bools, 0 = int32

// ---------------- helpers ----------------
__device__ __forceinline__ unsigned encf(float f) {
    unsigned u = __float_as_uint(f);
    return (u & 0x80000000u) ? ~u : (u | 0x80000000u);
}
__device__ __forceinline__ float decf(unsigned v) {
    return (v & 0x80000000u) ? __uint_as_float(v ^ 0x80000000u) : __uint_as_float(~v);
}
__device__ __forceinline__ float sgm(float x) { return 1.0f / (1.0f + __expf(-x)); }

__device__ __forceinline__ int ldmask(const void* p, int i) {
    return g_mflag ? (int)((const unsigned char*)p)[i] : ((const int*)p)[i];
}

__device__ __forceinline__ unsigned long long packdup(float a) {
    unsigned long long r; unsigned u = __float_as_uint(a);
    asm("mov.b64 %0, {%1, %1};" : "=l"(r) : "r"(u));
    return r;
}
__device__ __forceinline__ float2 unpk(unsigned long long v) {
    float2 f;
    asm("mov.b64 {%0, %1}, %2;" : "=f"(f.x), "=f"(f.y) : "l"(v));
    return f;
}
#define FMA2(acc, a, b) asm("fma.rn.f32x2 %0, %1, %2, %0;" : "+l"(acc) : "l"(a), "l"(b))

__device__ __forceinline__ void red_v4(float* p, float4 v) {
    asm volatile("red.global.add.v4.f32 [%0], {%1,%2,%3,%4};"
                 :: "l"(p), "f"(v.x), "f"(v.y), "f"(v.z), "f"(v.w) : "memory");
}

#define INSTRIDE 132                           // padded row stride (floats)
#define SMEM_BIG (2*128*INSTRIDE*4)            // 135168 B
#define SMEM_UPD ((128*INSTRIDE + 64*INSTRIDE)*4)

// ---------------- mask dtype detection ----------------
// If masks are int32 (little-endian 0/1), every byte at offset %4 != 0 within
// the first BEc bytes is zero. If they are genuine 1-byte bools, those offsets
// hold random 0/1 values and are almost surely nonzero somewhere.
__global__ void detect_kernel(const unsigned char* __restrict__ emk) {
    int tid = threadIdx.x;
    int any = 0;
    for (int i = tid; i < BEc; i += 256)
        if ((i & 3) && emk[i]) any = 1;
    any = __syncthreads_or(any);
    if (tid == 0) g_mflag = any;
}

// ---------------- P0: per-relation tables ----------------
__global__ void rel_tables_kernel(const float* __restrict__ rel_table,
                                  const float* __restrict__ den_W1,
                                  const float* __restrict__ msg_W,
                                  const float* __restrict__ msg_b,
                                  const float* __restrict__ beta_W,
                                  const float* __restrict__ att_W) {
    __shared__ float hr[8][Dc];
    int j = threadIdx.x;
    int r0 = blockIdx.x * 8;                 // 125 blocks * 8 = 1000
    #pragma unroll
    for (int u = 0; u < 8; u++) hr[u][j] = rel_table[(r0 + u) * Dc + j];
    __syncthreads();
    float aD[8] = {0}, a0[8] = {0}, a1[8] = {0}, a2[8] = {0};
    for (int i = 0; i < Dc; i++) {
        float wD = den_W1[i * Dc + j];
        float w0 = msg_W[(0 * 640 + 384 + i) * Dc + j];
        float w1 = msg_W[(1 * 640 + 384 + i) * Dc + j];
        float w2 = msg_W[(2 * 640 + 384 + i) * Dc + j];
        #pragma unroll
        for (int u = 0; u < 8; u++) {
            float h = hr[u][i];
            aD[u] += h * wD; a0[u] += h * w0; a1[u] += h * w1; a2[u] += h * w2;
        }
    }
    float b0 = msg_b[j], b1 = msg_b[Dc + j], b2 = msg_b[2 * Dc + j];
    #pragma unroll
    for (int u = 0; u < 8; u++) {
        int r = r0 + u;
        g_relDen[r * Dc + j] = aD[u];
        g_relMsg[(0 * NRELc + r) * Dc + j] = a0[u] + b0;
        g_relMsg[(1 * NRELc + r) * Dc + j] = a1[u] + b1;
        g_relMsg[(2 * NRELc + r) * Dc + j] = a2[u] + b2;
    }
    if (j < 8) {
        float s = 0;
        for (int i = 0; i < Dc; i++) s += hr[j][i] * beta_W[i];
        g_relBeta[r0 + j] = s;
    } else if (j < 32) {
        int t = j - 8; int u = t / 3, k = t % 3;
        float s = 0;
        for (int i = 0; i < Dc; i++) s += hr[u][i] * att_W[k * 384 + 128 + i];
        g_relAtt[k * NRELc + (r0 + u)] = s;
    }
}

// ---------------- P0b: per-batch vectors ----------------
__global__ void batch_vecs_kernel(const float* __restrict__ rq,
                                  const float* __restrict__ den_W1,
                                  const float* __restrict__ den_b1,
                                  const float* __restrict__ msg_W,
                                  const float* __restrict__ beta_W,
                                  const float* __restrict__ beta_b,
                                  const float* __restrict__ att_W,
                                  const float* __restrict__ att_b) {
    int j = threadIdx.x;
    for (int b = 0; b < Bc; b++) {
        float acc = 0;
        for (int i = 0; i < Dc; i++) acc += rq[b * Dc + i] * den_W1[(Dc + i) * Dc + j];
        g_rqDen[b * Dc + j] = acc + den_b1[j];
    }
    for (int k = 0; k < Lc; k++) {
        float s = 0;
        for (int i = 0; i < Dc; i++) s += msg_W[(k * 640 + 256 + i) * Dc + j];
        g_s3[k * Dc + j] = s;
    }
    if (j < Bc) {
        float s = 0;
        for (int i = 0; i < Dc; i++) s += rq[j * Dc + i] * beta_W[i];
        g_rqBeta[j] = s + beta_b[0];
    }
    if (j < Lc * Bc) {
        int k = j / Bc, b = j % Bc;
        float s = 0;
        for (int i = 0; i < Dc; i++) s += rq[b * Dc + i] * att_W[k * 384 + 256 + i];
        g_rqAtt[k * Bc + b] = s + att_b[k];
    }
}

// ---------------- P1: per-edge scalars (den/gate) — conf GEMM ----------------
__global__ void __launch_bounds__(256, 1)
p1_kernel(const int* __restrict__ rels_g, const float* __restrict__ scores,
          const void* __restrict__ ecm, const void* __restrict__ emk,
          const float* __restrict__ conf, const float* __restrict__ den_W1,
          const float* __restrict__ den_W2, const float* __restrict__ den_b2) {
    extern __shared__ float smem[];
    float* In = smem;
    float* Ws = smem + 128 * INSTRIDE;
    __shared__ int s_rel[128];
    int tid = threadIdx.x;
    int e0 = blockIdx.x * 128;
    int b = e0 >> 15;
    if (tid < 128) s_rel[tid] = rels_g[e0 + tid];
    int w = tid >> 5, l = tid & 31;
    #pragma unroll
    for (int rr = 0; rr < 16; rr++) {
        int e = w * 16 + rr;
        *(float4*)&In[e * INSTRIDE + 4 * l] = *(const float4*)&conf[((size_t)(e0 + e)) * Dc + 4 * l];
        *(float4*)&Ws[e * INSTRIDE + 4 * l] = *(const float4*)&den_W1[(256 + e) * Dc + 4 * l];
    }
    __syncthreads();

    int ty = tid >> 4, tx = tid & 15;
    unsigned long long acc[8][4] = {};
    const float* inb[8];
    #pragma unroll
    for (int r = 0; r < 8; r++) inb[r] = &In[(ty * 8 + r) * INSTRIDE];
    #pragma unroll 4
    for (int kk = 0; kk < Dc; kk++) {
        const ulonglong2* wp = (const ulonglong2*)&Ws[kk * INSTRIDE + tx * 8];
        ulonglong2 wa = wp[0], wb = wp[1];
        #pragma unroll
        for (int r = 0; r < 8; r++) {
            unsigned long long a2 = packdup(inb[r][kk]);
            FMA2(acc[r][0], a2, wa.x); FMA2(acc[r][1], a2, wa.y);
            FMA2(acc[r][2], a2, wb.x); FMA2(acc[r][3], a2, wb.y);
        }
    }
    __syncthreads();

    float dw2[8];
    #pragma unroll
    for (int c = 0; c < 8; c++) dw2[c] = den_W2[tx * 8 + c];
    float* red = In;  // reuse
    const float* qd = &g_rqDen[b * Dc];
    #pragma unroll
    for (int r = 0; r < 8; r++) {
        int e = ty * 8 + r;
        const float* rd = &g_relDen[s_rel[e] * Dc];
        float vout[8];
        #pragma unroll
        for (int q = 0; q < 4; q++) { float2 u = unpk(acc[r][q]); vout[2*q] = u.x; vout[2*q+1] = u.y; }
        float p = 0;
        #pragma unroll
        for (int c = 0; c < 8; c++) {
            int j = tx * 8 + c;
            float v = vout[c] + rd[j] + qd[j];
            p += fmaxf(v, 0.0f) * dw2[c];
        }
        red[e * 17 + tx] = p;
    }
    __syncthreads();
    if (tid < 128) {
        int e = tid, glob = e0 + e, rel = s_rel[e];
        float s = 0;
        #pragma unroll
        for (int t = 0; t < 16; t++) s += red[e * 17 + t];
        float den = sgm(s + den_b2[0]);
        den *= ldmask(emk, glob) ? 1.0f : 0.0f;
        float beta = sgm(g_relBeta[rel] + g_rqBeta[b]);
        float gate = ldmask(ecm, glob) ? sgm((scores[glob] - beta) * 10.0f) : 0.5f;
        g_gd[glob] = gate * den;
        #pragma unroll
        for (int k = 0; k < Lc; k++)
            g_attc[k * BEc + glob] = g_relAtt[k * NRELc + rel] + g_rqAtt[k * Bc + b];
    }
}

// ---------------- per-layer init ----------------
__global__ void init_kernel(int doH) {
    int idx = blockIdx.x * blockDim.x + threadIdx.x;   // B*N*D threads
    g_aggr[idx] = 0.0f;
    if (doH) {
        int n = (idx >> 7) & (Nc - 1);
        g_h[idx] = (n == 0) ? 1.0f : 0.0f;
    }
    if (idx < Bc * Nc) {
        g_mx[idx] = encf(-1.0e9f);
        g_sm[idx] = 0.0f;
    }
}

// ---------------- K1: message GEMM + attention logits ----------------
__global__ void __launch_bounds__(256, 1)
msg_kernel(int k, const int* __restrict__ edge_index, const int* __restrict__ rels_g,
           const void* __restrict__ emk, const float* __restrict__ conf,
           const float* __restrict__ rel_table, const float* __restrict__ msg_W,
           const float* __restrict__ att_W) {
    extern __shared__ float smem[];
    float* In = smem;
    float* Ws = smem + 128 * INSTRIDE;
    __shared__ int s_src[128];
    __shared__ int s_rel[128];
    int tid = threadIdx.x;
    int e0 = blockIdx.x * 128;
    int b = e0 >> 15;
    int ebi0 = e0 & (Ec - 1);
    if (tid < 128) {
        s_src[tid] = edge_index[(size_t)b * 2 * Ec + ebi0 + tid];
        s_rel[tid] = rels_g[e0 + tid];
    }
    __syncthreads();
    int w = tid >> 5, l = tid & 31, ty = tid >> 4, tx = tid & 15;
    unsigned long long acc[8][4] = {};

    const int rowbase[3] = {0, 128, 512};   // W1 (h*hr), W2 (h), W5 (conf)
    for (int ph = 0; ph < 3; ph++) {
        #pragma unroll
        for (int rr = 0; rr < 16; rr++) {
            int e = w * 16 + rr;
            float4 v;
            if (ph == 2) {
                v = *(const float4*)&conf[((size_t)(e0 + e)) * Dc + 4 * l];
            } else {
                float4 hv = *(const float4*)&g_h[((size_t)(b * Nc + s_src[e])) * Dc + 4 * l];
                if (ph == 0) {
                    float4 rv = *(const float4*)&rel_table[(size_t)s_rel[e] * Dc + 4 * l];
                    v = make_float4(hv.x * rv.x, hv.y * rv.y, hv.z * rv.z, hv.w * rv.w);
                } else v = hv;
            }
            *(float4*)&In[e * INSTRIDE + 4 * l] = v;
            *(float4*)&Ws[e * INSTRIDE + 4 * l] =
                *(const float4*)&msg_W[((size_t)k * 640 + rowbase[ph] + e) * Dc + 4 * l];
        }
        __syncthreads();
        const float* inb[8];
        #pragma unroll
        for (int r = 0; r < 8; r++) inb[r] = &In[(ty * 8 + r) * INSTRIDE];
        #pragma unroll 4
        for (int kk = 0; kk < Dc; kk++) {
            const ulonglong2* wp = (const ulonglong2*)&Ws[kk * INSTRIDE + tx * 8];
            ulonglong2 wa = wp[0], wb = wp[1];
            #pragma unroll
            for (int r = 0; r < 8; r++) {
                unsigned long long a2 = packdup(inb[r][kk]);
                FMA2(acc[r][0], a2, wa.x); FMA2(acc[r][1], a2, wa.y);
                FMA2(acc[r][2], a2, wb.x); FMA2(acc[r][3], a2, wb.y);
            }
        }
        __syncthreads();
    }

    // epilogue: table add + relu + att partial + store raw messages
    float aw[8];
    #pragma unroll
    for (int c = 0; c < 8; c++) aw[c] = att_W[(size_t)k * 384 + tx * 8 + c];
    float* red = In;  // reuse
    #pragma unroll
    for (int r = 0; r < 8; r++) {
        int e = ty * 8 + r;
        int glob = e0 + e;
        int rel = s_rel[e];
        bool z0 = (s_src[e] == 0);
        const float* rm = &g_relMsg[((size_t)k * NRELc + rel) * Dc];
        const float* s3 = &g_s3[k * Dc];
        float vout[8];
        #pragma unroll
        for (int q = 0; q < 4; q++) { float2 u = unpk(acc[r][q]); vout[2*q] = u.x; vout[2*q+1] = u.y; }
        float p = 0;
        #pragma unroll
        for (int c = 0; c < 8; c++) {
            int j = tx * 8 + c;
            float v = vout[c] + rm[j];
            if (z0) v += s3[j];
            v = fmaxf(v, 0.0f);
            vout[c] = v;
            p += v * aw[c];
        }
        *(float4*)&g_raw[((size_t)glob) * Dc + tx * 8]     = make_float4(vout[0], vout[1], vout[2], vout[3]);
        *(float4*)&g_raw[((size_t)glob) * Dc + tx * 8 + 4] = make_float4(vout[4], vout[5], vout[6], vout[7]);
        red[e * 17 + tx] = p;
    }
    __syncthreads();
    if (tid < 128) {
        int e = tid, glob = e0 + e;
        float s = 0;
        #pragma unroll
        for (int t = 0; t < 16; t++) s += red[e * 17 + t];
        float att = s + g_attc[(size_t)k * BEc + glob];
        att = att > 0.0f ? att : 0.01f * att;
        if (!ldmask(emk, glob)) att = -1.0e9f;
        g_att[glob] = att;
        int ebi = glob & (Ec - 1);
        int tgt = edge_index[(size_t)(b * 2 + 1) * Ec + ebi];
        atomicMax(&g_mx[b * Nc + tgt], encf(att));
    }
}

// ---------------- K2: softmax denominator ----------------
__global__ void softden_kernel(const int* __restrict__ edge_index) {
    int glob = blockIdx.x * blockDim.x + threadIdx.x;
    if (glob >= BEc) return;
    int b = glob >> 15, ebi = glob & (Ec - 1);
    int tgt = edge_index[(size_t)(b * 2 + 1) * Ec + ebi];
    float m = decf(g_mx[b * Nc + tgt]);
    float ex = __expf(g_att[glob] - m);
    atomicAdd(&g_sm[b * Nc + tgt], ex);
}

// ---------------- K3: weighted message scatter ----------------
__global__ void scatter_kernel(const int* __restrict__ edge_index) {
    int gt = blockIdx.x * blockDim.x + threadIdx.x;
    int glob = gt >> 5;
    int l = threadIdx.x & 31;
    if (glob >= BEc) return;
    int b = glob >> 15, ebi = glob & (Ec - 1);
    float wv = 0.0f;
    int tgt = 0;
    if (l == 0) {
        tgt = edge_index[(size_t)(b * 2 + 1) * Ec + ebi];
        float gd = g_gd[glob];
        if (gd != 0.0f) {
            int node = b * Nc + tgt;
            float m = decf(g_mx[node]);
            float sden = g_sm[node];
            wv = gd * __expf(g_att[glob] - m) / (sden + 1e-8f);
        }
    }
    wv  = __shfl_sync(0xffffffffu, wv, 0);
    tgt = __shfl_sync(0xffffffffu, tgt, 0);
    if (wv != 0.0f) {
        float4 rm = *(const float4*)&g_raw[((size_t)glob) * Dc + 4 * l];
        float4 v = make_float4(wv * rm.x, wv * rm.y, wv * rm.z, wv * rm.w);
        red_v4(&g_aggr[((size_t)(b * Nc + tgt)) * Dc + 4 * l], v);
    }
}

// ---------------- K4: node update GEMM + LayerNorm ----------------
__global__ void __launch_bounds__(256, 1)
upd_kernel(int k, const float* __restrict__ upd_W, const float* __restrict__ upd_b,
           const float* __restrict__ ln_g, const float* __restrict__ ln_b,
           float* __restrict__ out) {
    extern __shared__ float smem[];
    float* Ws = smem;                    // 128 x 132
    float* Ag = smem + 128 * INSTRIDE;   // 64 x 132 (later reused as reduction scratch)
    __shared__ float mus[64], rst[64];
    int tid = threadIdx.x;
    int w = tid >> 5, l = tid & 31;
    int n0 = blockIdx.x * 64;
    #pragma unroll
    for (int rr = 0; rr < 16; rr++) {
        int kk = w * 16 + rr;
        *(float4*)&Ws[kk * INSTRIDE + 4 * l] = *(const float4*)&upd_W[((size_t)k * Dc + kk) * Dc + 4 * l];
    }
    #pragma unroll
    for (int rr = 0; rr < 8; rr++) {
        int nl = w * 8 + rr;
        *(float4*)&Ag[nl * INSTRIDE + 4 * l] = *(const float4*)&g_aggr[((size_t)(n0 + nl)) * Dc + 4 * l];
    }
    __syncthreads();
    int ty = tid >> 4, tx = tid & 15;
    unsigned long long acc[4][4] = {};
    const float* inb[4];
    #pragma unroll
    for (int r = 0; r < 4; r++) inb[r] = &Ag[(ty * 4 + r) * INSTRIDE];
    #pragma unroll 4
    for (int kk = 0; kk < Dc; kk++) {
        const ulonglong2* wp = (const ulonglong2*)&Ws[kk * INSTRIDE + tx * 8];
        ulonglong2 wa = wp[0], wb = wp[1];
        #pragma unroll
        for (int r = 0; r < 4; r++) {
            unsigned long long a2 = packdup(inb[r][kk]);
            FMA2(acc[r][0], a2, wa.x); FMA2(acc[r][1], a2, wa.y);
            FMA2(acc[r][2], a2, wb.x); FMA2(acc[r][3], a2, wb.y);
        }
    }
    __syncthreads();

    float vbuf[4][8];
    float s1[4] = {0}, s2[4] = {0};
    #pragma unroll
    for (int r = 0; r < 4; r++) {
        int n = n0 + ty * 4 + r;
        float vout[8];
        #pragma unroll
        for (int q = 0; q < 4; q++) { float2 u = unpk(acc[r][q]); vout[2*q] = u.x; vout[2*q+1] = u.y; }
        #pragma unroll
        for (int c = 0; c < 8; c++) {
            int j = tx * 8 + c;
            float v = g_h[((size_t)n) * Dc + j] + vout[c] + upd_b[k * Dc + j];
            vbuf[r][c] = v;
            s1[r] += v;
            s2[r] += v * v;
        }
    }
    float* red1 = Ag;
    float* red2 = Ag + 64 * 17;
    #pragma unroll
    for (int r = 0; r < 4; r++) {
        red1[(ty * 4 + r) * 17 + tx] = s1[r];
        red2[(ty * 4 + r) * 17 + tx] = s2[r];
    }
    __syncthreads();
    if (tid < 64) {
        float a = 0, bb = 0;
        #pragma unroll
        for (int t = 0; t < 16; t++) { a += red1[tid * 17 + t]; bb += red2[tid * 17 + t]; }
        float mu = a * (1.0f / Dc);
        float var = bb * (1.0f / Dc) - mu * mu;
        mus[tid] = mu;
        rst[tid] = rsqrtf(var + 1e-5f);
    }
    __syncthreads();
    #pragma unroll
    for (int r = 0; r < 4; r++) {
        int nl = ty * 4 + r;
        int n = n0 + nl;
        float mu = mus[nl], rs = rst[nl];
        float y[8];
        #pragma unroll
        for (int c = 0; c < 8; c++) {
            int j = tx * 8 + c;
            y[c] = (vbuf[r][c] - mu) * rs * ln_g[j] + ln_b[j];
        }
        *(float4*)&g_h[((size_t)n) * Dc + tx * 8]     = make_float4(y[0], y[1], y[2], y[3]);
        *(float4*)&g_h[((size_t)n) * Dc + tx * 8 + 4] = make_float4(y[4], y[5], y[6], y[7]);
        if ((n & (Nc - 1)) == 0) {
            int b = n >> 11;
            #pragma unroll
            for (int c = 0; c < 8; c++) out[((size_t)b * Lc + k) * Dc + tx * 8 + c] = y[c];
        }
    }
}

// ---------------- launch ----------------
extern "C" void kernel_launch(void* const* d_in, const int* in_sizes, int n_in,
                              void* d_out, int out_size) {
    const int*   edge_index = (const int*)d_in[0];
    const int*   rels       = (const int*)d_in[1];
    const float* scores     = (const float*)d_in[2];
    const void*  ecm        = d_in[3];
    const void*  emk        = d_in[4];
    // d_in[5] = mask (unused)
    const float* rq         = (const float*)d_in[6];
    const float* conf       = (const float*)d_in[7];
    const float* rel_table  = (const float*)d_in[8];
    const float* beta_W     = (const float*)d_in[9];
    const float* beta_b     = (const float*)d_in[10];
    const float* msg_W      = (const float*)d_in[11];
    const float* msg_b      = (const float*)d_in[12];
    const float* upd_W      = (const float*)d_in[13];
    const float* upd_b      = (const float*)d_in[14];
    const float* ln_g       = (const float*)d_in[15];
    const float* ln_b       = (const float*)d_in[16];
    const float* att_W      = (const float*)d_in[17];
    const float* att_b      = (const float*)d_in[18];
    const float* den_W1     = (const float*)d_in[19];
    const float* den_b1     = (const float*)d_in[20];
    const float* den_W2     = (const float*)d_in[21];
    const float* den_b2     = (const float*)d_in[22];
    float* out = (float*)d_out;

    cudaFuncSetAttribute(p1_kernel,  cudaFuncAttributeMaxDynamicSharedMemorySize, SMEM_BIG);
    cudaFuncSetAttribute(msg_kernel, cudaFuncAttributeMaxDynamicSharedMemorySize, SMEM_BIG);
    cudaFuncSetAttribute(upd_kernel, cudaFuncAttributeMaxDynamicSharedMemorySize, SMEM_UPD);

    detect_kernel<<<1, 256>>>((const unsigned char*)emk);
    rel_tables_kernel<<<125, 128>>>(rel_table, den_W1, msg_W, msg_b, beta_W, att_W);
    batch_vecs_kernel<<<1, 128>>>(rq, den_W1, den_b1, msg_W, beta_W, beta_b, att_W, att_b);
    p1_kernel<<<BEc / 128, 256, SMEM_BIG>>>(rels, scores, ecm, emk, conf, den_W1, den_W2, den_b2);

    for (int k = 0; k < Lc; k++) {
        init_kernel<<<(Bc * Nc * Dc) / 256, 256>>>(k == 0);
        msg_kernel<<<BEc / 128, 256, SMEM_BIG>>>(k, edge_index, rels, emk, conf,
                                                 rel_table, msg_W, att_W);
        softden_kernel<<<BEc / 256, 256>>>(edge_index);
        scatter_kernel<<<(BEc * 32) / 256, 256>>>(edge_index);
        upd_kernel<<<(Bc * Nc) / 64, 256, SMEM_UPD>>>(k, upd_W, upd_b, ln_g, ln_b, out);
    }
}